// round 1
// baseline (speedup 1.0000x reference)
#include <cuda_runtime.h>
#include <cstdint>
#include <math.h>

// Problem constants
#define NUM_E 1024
#define DIM   64
#define TT    2048
#define BB    32
#define NROWS (BB * TT)          // 65536 rows (b*t)
#define NELEM (BB * DIM * TT)    // 4194304 elements of x / quantized
#define CHUNK 256                // codes per smem chunk

// Output layout (tuple flattened in reference order, all fp32)
#define Q_OFF      0
#define COMMIT_OFF 4194304
#define PERP_OFF   4194305
#define AVG_OFF    4194306
#define IDX_OFF    4195330
#define USAGE_OFF  4260866

// Device scratch (no allocations allowed)
__device__ int   g_idx[NROWS];
__device__ int   g_counts[NUM_E];
__device__ float g_sumsq;
__device__ float g_e2[NUM_E];

// ---- packed f32x2 helpers (FFMA2 only reachable via PTX on sm_103a) ----
__device__ __forceinline__ void fma2(unsigned long long& acc,
                                     unsigned long long a,
                                     unsigned long long b) {
    asm("fma.rn.f32x2 %0, %1, %2, %0;" : "+l"(acc) : "l"(a), "l"(b));
}
__device__ __forceinline__ void add2(unsigned long long& d,
                                     unsigned long long a,
                                     unsigned long long b) {
    asm("add.rn.f32x2 %0, %1, %2;" : "=l"(d) : "l"(a), "l"(b));
}
__device__ __forceinline__ unsigned long long pack2(float lo, float hi) {
    unsigned long long r;
    asm("mov.b64 %0, {%1, %2};" : "=l"(r) : "f"(lo), "f"(hi));
    return r;
}
__device__ __forceinline__ float2 unpack2(unsigned long long v) {
    float2 r;
    asm("mov.b64 {%0, %1}, %2;" : "=f"(r.x), "=f"(r.y) : "l"(v));
    return r;
}

// ---- prep: codebook norms + zero scratch ----
__global__ void prep_kernel(const float* __restrict__ embed) {
    int tid = threadIdx.x;  // 1024 threads, one per code
    const float4* e = (const float4*)(embed + (size_t)tid * DIM);
    float s = 0.f;
#pragma unroll
    for (int i = 0; i < DIM / 4; i++) {
        float4 v = e[i];
        s += v.x * v.x + v.y * v.y + v.z * v.z + v.w * v.w;
    }
    g_e2[tid] = s;
    g_counts[tid] = 0;
    if (tid == 0) g_sumsq = 0.f;
}

// ---- main: fused distance-argmin + histogram ----
// One thread per row. x row (64 floats, stride TT in gmem but coalesced across
// the warp) packed into 32 u64 f32x2 registers. Codebook streamed through SMEM
// in 64KB chunks; all lanes read the same code row -> broadcast, conflict-free.
__global__ void __launch_bounds__(256)
vq_argmin_kernel(const float* __restrict__ x,
                 const float* __restrict__ embed,
                 float* __restrict__ out_idx) {
    extern __shared__ float sm[];
    float* sE    = sm;                          // [CHUNK][DIM]
    float* sE2   = sm + CHUNK * DIM;            // [CHUNK]
    int*   shist = (int*)(sm + CHUNK * DIM + CHUNK);  // [NUM_E]

    const int tid = threadIdx.x;
    for (int i = tid; i < NUM_E; i += 256) shist[i] = 0;

    const int row = blockIdx.x * 256 + tid;
    const int b_i = row >> 11;
    const int t_i = row & (TT - 1);
    const float* xp = x + (size_t)b_i * DIM * TT + t_i;

    unsigned long long xr[DIM / 2];
#pragma unroll
    for (int j = 0; j < DIM / 2; j++) {
        float lo = xp[(size_t)(2 * j) * TT];
        float hi = xp[(size_t)(2 * j + 1) * TT];
        xr[j] = pack2(lo, hi);
    }

    float best = 3.4e38f;
    int bidx = 0;

    for (int k0 = 0; k0 < NUM_E; k0 += CHUNK) {
        __syncthreads();
        {
            // cooperative chunk load: CHUNK*DIM floats = 4096 float4, 16/thread
            const float4* src = (const float4*)(embed + (size_t)k0 * DIM);
            float4* dst = (float4*)sE;
#pragma unroll
            for (int i = 0; i < (CHUNK * DIM / 4) / 256; i++)
                dst[tid + i * 256] = src[tid + i * 256];
            if (tid < CHUNK) sE2[tid] = g_e2[k0 + tid];
        }
        __syncthreads();

#pragma unroll 2
        for (int c = 0; c < CHUNK; c++) {
            const ulonglong2* ev = (const ulonglong2*)(sE + c * DIM);
            unsigned long long a0 = 0ull, a1 = 0ull, a2 = 0ull, a3 = 0ull;
#pragma unroll
            for (int i = 0; i < 16; i++) {
                ulonglong2 e = ev[i];   // one LDS.128 = 2 packed pairs
                if ((i & 1) == 0) {
                    fma2(a0, xr[2 * i], e.x);
                    fma2(a1, xr[2 * i + 1], e.y);
                } else {
                    fma2(a2, xr[2 * i], e.x);
                    fma2(a3, xr[2 * i + 1], e.y);
                }
            }
            unsigned long long s0, s1;
            add2(s0, a0, a2);
            add2(s1, a1, a3);
            add2(s0, s0, s1);
            float2 f = unpack2(s0);
            float dot = f.x + f.y;
            float score = fmaf(-2.0f, dot, sE2[c]);  // ||x||^2 const per row: drop
            if (score < best) { best = score; bidx = k0 + c; }  // strict < = first-min tie-break
        }
    }

    g_idx[row] = bidx;
    out_idx[row] = (float)bidx;
    atomicAdd(&shist[bidx], 1);
    __syncthreads();
    for (int i = tid; i < NUM_E; i += 256) {
        int v = shist[i];
        if (v) atomicAdd(&g_counts[i], v);
    }
}

// ---- gather + straight-through + commitment-loss reduction ----
__global__ void gather_kernel(const float* __restrict__ x,
                              const float* __restrict__ embed,
                              float* __restrict__ out_q) {
    __shared__ float warpsum[8];
    const int gid = blockIdx.x * blockDim.x + threadIdx.x;
    const int lin = gid * 4;               // 4 consecutive t per thread
    const int t_i = lin & (TT - 1);
    const int d_i = (lin >> 11) & (DIM - 1);
    const int b_i = lin >> 17;

    float4 xv = *(const float4*)(x + lin);
    const int rowbase = (b_i << 11) + t_i;         // multiple of 4
    int4 id = *(const int4*)(g_idx + rowbase);

    float q0 = embed[id.x * DIM + d_i];
    float q1 = embed[id.y * DIM + d_i];
    float q2 = embed[id.z * DIM + d_i];
    float q3 = embed[id.w * DIM + d_i];

    float d0 = q0 - xv.x, d1 = q1 - xv.y, d2 = q2 - xv.z, d3 = q3 - xv.w;
    // straight-through: x + (q - x), matching reference fp ordering
    float4 ov = make_float4(xv.x + d0, xv.y + d1, xv.z + d2, xv.w + d3);
    *(float4*)(out_q + lin) = ov;

    float s = d0 * d0 + d1 * d1 + d2 * d2 + d3 * d3;
#pragma unroll
    for (int o = 16; o; o >>= 1) s += __shfl_down_sync(0xffffffffu, s, o);
    const int lane = threadIdx.x & 31, w = threadIdx.x >> 5;
    if (lane == 0) warpsum[w] = s;
    __syncthreads();
    if (w == 0) {
        float v = lane < 8 ? warpsum[lane] : 0.f;
#pragma unroll
        for (int o = 4; o; o >>= 1) v += __shfl_down_sync(0xffffffffu, v, o);
        if (lane == 0) atomicAdd(&g_sumsq, v);
    }
}

// ---- finalize: avg_probs, perplexity, usage loss, commitment loss ----
__global__ void finalize_kernel(float* __restrict__ out) {
    __shared__ float s1[32], s2[32];
    const int tid = threadIdx.x;  // 1024 threads, one per code
    float p = (float)g_counts[tid] * (1.0f / (float)NROWS);
    out[AVG_OFF + tid] = p;
    float t1 = p * logf(p + 1e-10f);
    float t2 = p * logf(p * (float)NUM_E + 1e-10f);
#pragma unroll
    for (int o = 16; o; o >>= 1) {
        t1 += __shfl_down_sync(0xffffffffu, t1, o);
        t2 += __shfl_down_sync(0xffffffffu, t2, o);
    }
    const int lane = tid & 31, w = tid >> 5;
    if (lane == 0) { s1[w] = t1; s2[w] = t2; }
    __syncthreads();
    if (w == 0) {
        float a = s1[lane], b = s2[lane];
#pragma unroll
        for (int o = 16; o; o >>= 1) {
            a += __shfl_down_sync(0xffffffffu, a, o);
            b += __shfl_down_sync(0xffffffffu, b, o);
        }
        if (lane == 0) {
            out[PERP_OFF]   = expf(-a);
            out[USAGE_OFF]  = b;
            out[COMMIT_OFF] = 0.25f * g_sumsq / (float)NELEM;
        }
    }
}

extern "C" void kernel_launch(void* const* d_in, const int* in_sizes, int n_in,
                              void* d_out, int out_size) {
    const float* x     = (const float*)d_in[0];
    const float* embed = (const float*)d_in[1];
    float* out = (float*)d_out;

    const int smem = (CHUNK * DIM + CHUNK) * 4 + NUM_E * 4;  // 70656 B
    cudaFuncSetAttribute(vq_argmin_kernel,
                         cudaFuncAttributeMaxDynamicSharedMemorySize, smem);

    prep_kernel<<<1, 1024>>>(embed);
    vq_argmin_kernel<<<NROWS / 256, 256, smem>>>(x, embed, out + IDX_OFF);
    gather_kernel<<<NELEM / (256 * 4), 256>>>(x, embed, out);
    finalize_kernel<<<1, 1024>>>(out);
}

// round 3
// speedup vs baseline: 1.2855x; 1.2855x over previous
#include <cuda_runtime.h>
#include <cuda_bf16.h>
#include <cstdint>
#include <math.h>

// ---------------- problem constants ----------------
#define NUM_E 1024
#define DIM   64
#define TT    2048
#define BB    32
#define NROWS (BB * TT)          // 65536
#define NELEM (BB * DIM * TT)    // 4194304

// output layout (flattened tuple, fp32)
#define COMMIT_OFF 4194304
#define PERP_OFF   4194305
#define AVG_OFF    4194306
#define IDX_OFF    4195330
#define USAGE_OFF  4260866

// ---------------- tiling ----------------
#define ROWS_CTA 256                  // rows per CTA (16 m-tiles)
#define NCH      8                    // code chunks of 128
#define CHB      49152                // bytes per packed B chunk: 12*16*256

// smem offsets
#define SA_OFF   0                    // A frags: 16 mt * 12 pkt * 32 * 16B = 96KB
#define SB_OFF   98304                // B frags: 2 * 48KB
#define SE2_OFF  196608               // 4KB
#define SRF_OFF  200704               // reduce floats 512*4
#define SRI_OFF  202752               // reduce ints   512*4
#define SMEM_DYN 204800

// ---------------- device scratch ----------------
__device__ __align__(16) unsigned char g_Bp[NCH * CHB];  // packed B frags
__device__ float g_e2[NUM_E];
__device__ int   g_idx[NROWS];
__device__ int   g_counts[NUM_E];
__device__ float g_sumsq;

// ---------------- helpers ----------------
__device__ __forceinline__ uint32_t smem_u32(const void* p) {
    uint32_t a;
    asm("{ .reg .u64 t; cvta.to.shared.u64 t, %1; cvt.u32.u64 %0, t; }" : "=r"(a) : "l"(p));
    return a;
}
__device__ __forceinline__ void cp16(uint32_t saddr, const void* g) {
    asm volatile("cp.async.cg.shared.global [%0], [%1], 16;" :: "r"(saddr), "l"(g));
}
__device__ __forceinline__ void cp_commit() {
    asm volatile("cp.async.commit_group;" ::: "memory");
}
__device__ __forceinline__ void mma16816(float* d, const uint4 a, const uint2 b) {
    asm volatile(
        "mma.sync.aligned.m16n8k16.row.col.f32.bf16.bf16.f32 "
        "{%0,%1,%2,%3}, {%4,%5,%6,%7}, {%8,%9}, {%0,%1,%2,%3};"
        : "+f"(d[0]), "+f"(d[1]), "+f"(d[2]), "+f"(d[3])
        : "r"(a.x), "r"(a.y), "r"(a.z), "r"(a.w), "r"(b.x), "r"(b.y));
}
__device__ __forceinline__ void split3(float v, uint32_t& h0, uint32_t& h1, uint32_t& h2) {
    __nv_bfloat16 b0 = __float2bfloat16(v);
    float f0 = __bfloat162float(b0);
    float r1 = v - f0;
    __nv_bfloat16 b1 = __float2bfloat16(r1);
    float f1 = __bfloat162float(b1);
    __nv_bfloat16 b2 = __float2bfloat16(r1 - f1);
    h0 = (uint32_t)*reinterpret_cast<unsigned short*>(&b0);
    h1 = (uint32_t)*reinterpret_cast<unsigned short*>(&b1);
    h2 = (uint32_t)*reinterpret_cast<unsigned short*>(&b2);
}

// ---------------- prep: pack codebook into B-fragment layout + norms ----------------
__global__ void prep_kernel(const float* __restrict__ embed) {
    const int c = threadIdx.x;            // 1024 threads, one per code
    const float* e = embed + (size_t)c * DIM;
    uint32_t h0[32], h1[32], h2[32];
    float s = 0.f;
#pragma unroll 8
    for (int j = 0; j < 32; ++j) {
        float2 v = *(const float2*)(e + 2 * j);
        s += v.x * v.x + v.y * v.y;
        uint32_t a0, a1, a2, b0, b1, b2;
        split3(v.x, a0, a1, a2);
        split3(v.y, b0, b1, b2);
        h0[j] = a0 | (b0 << 16);
        h1[j] = a1 | (b1 << 16);
        h2[j] = a2 | (b2 << 16);
    }
    g_e2[c] = s;
    g_counts[c] = 0;
    if (c == 0) g_sumsq = 0.f;

    const int chunk = c >> 7, n_in = c & 127, nt = n_in >> 3, lq = n_in & 7;
    uint32_t* dstb = (uint32_t*)(g_Bp + (size_t)chunk * CHB);
#pragma unroll
    for (int pkt = 0; pkt < 12; ++pkt) {
        const uint32_t* hp = (pkt < 4) ? h0 : (pkt < 8 ? h1 : h2);
        const int kb = (pkt & 3) * 8;
#pragma unroll
        for (int cc = 0; cc < 4; ++cc) {
            uint32_t* d = dstb + (((pkt * 16 + nt) * 32) + 4 * lq + cc) * 2;
            d[0] = hp[kb + cc];       // k = 2cc, 2cc+1
            d[1] = hp[kb + 4 + cc];   // k = 2cc+8, 2cc+9
        }
    }
}

// ---------------- main: HMMA distance GEMM + fused argmin ----------------
__global__ void __launch_bounds__(256, 1)
vq_mma_kernel(const float* __restrict__ x, float* __restrict__ out_idxf) {
    extern __shared__ char sm[];
    uint32_t* sA  = (uint32_t*)(sm + SA_OFF);
    float*    sE2 = (float*)(sm + SE2_OFF);
    float*    sRF = (float*)(sm + SRF_OFF);
    int*      sRI = (int*)(sm + SRI_OFF);
    const uint32_t sBaddr = smem_u32(sm + SB_OFF);

    const int tid = threadIdx.x, lane = tid & 31, w = tid >> 5;
    const int rg = w & 3, cg = w >> 2;   // 4 row-groups x 2 code-groups

    // prefetch B chunks 0,1
    {
        const char* src0 = (const char*)g_Bp;
        for (int k = tid; k < 3072; k += 256) cp16(sBaddr + k * 16, src0 + k * 16);
        cp_commit();
        const char* src1 = (const char*)g_Bp + CHB;
        for (int k = tid; k < 3072; k += 256) cp16(sBaddr + CHB + k * 16, src1 + k * 16);
        cp_commit();
    }

    // build A fragments (each thread packs one row)
    {
        const int r = tid;
        const int grow = blockIdx.x * ROWS_CTA + r;
        const float* xp = x + (size_t)(grow >> 11) * (DIM * TT) + (grow & (TT - 1));
        uint32_t h0[32], h1[32], h2[32];
#pragma unroll 8
        for (int j = 0; j < 32; ++j) {
            float va = xp[(size_t)(2 * j) * TT];
            float vb = xp[(size_t)(2 * j + 1) * TT];
            uint32_t a0, a1, a2, b0, b1, b2;
            split3(va, a0, a1, a2);
            split3(vb, b0, b1, b2);
            h0[j] = a0 | (b0 << 16);
            h1[j] = a1 | (b1 << 16);
            h2[j] = a2 | (b2 << 16);
        }
        const int mt = r >> 4, rr = r & 15;
        const int wsel = (rr < 8) ? 0 : 1;   // a0/a2 vs a1/a3
#pragma unroll
        for (int pkt = 0; pkt < 12; ++pkt) {
            const uint32_t* hp = (pkt < 4) ? h0 : (pkt < 8 ? h1 : h2);
            const int kb = (pkt & 3) * 8;
#pragma unroll
            for (int c = 0; c < 4; ++c) {
                uint32_t* dst = sA + (((mt * 12 + pkt) * 32) + 4 * (rr & 7) + c) * 4 + wsel;
                dst[0] = hp[kb + c];       // a0 / a1
                dst[2] = hp[kb + 4 + c];   // a2 / a3
            }
        }
        for (int i = tid; i < NUM_E; i += 256) sE2[i] = g_e2[i];
    }
    __syncthreads();

    // logical k-tile -> physical split tiles
    // A segs {x0,x0,x1,x1,x2,x0}, B segs {e0,e1,e0,e1,e0,e2}
    const int PA_[24] = {0,1,2,3, 0,1,2,3, 4,5,6,7, 4,5,6,7, 8,9,10,11, 0,1,2,3};
    const int PB_[24] = {0,1,2,3, 4,5,6,7, 0,1,2,3, 4,5,6,7, 0,1,2,3, 8,9,10,11};

    float best[8];
    int   bidx[8];
#pragma unroll
    for (int h = 0; h < 8; ++h) { best[h] = 3.4e38f; bidx[h] = 0; }

    for (int ch = 0; ch < NCH; ++ch) {
        if (ch < NCH - 1) asm volatile("cp.async.wait_group 1;" ::: "memory");
        else              asm volatile("cp.async.wait_group 0;" ::: "memory");
        __syncthreads();
        const uint32_t* Bb = (const uint32_t*)(sm + SB_OFF + (ch & 1) * CHB);

        float acc[4][8][4];
#pragma unroll
        for (int m = 0; m < 4; ++m)
#pragma unroll
            for (int n = 0; n < 8; ++n)
#pragma unroll
                for (int j = 0; j < 4; ++j) acc[m][n][j] = 0.f;

#pragma unroll
        for (int lkt = 0; lkt < 24; ++lkt) {
            const int pa = PA_[lkt], pb = PB_[lkt];
            uint4 Af[4];
#pragma unroll
            for (int m = 0; m < 4; ++m)
                Af[m] = *(const uint4*)(sA + ((((rg * 4 + m) * 12 + pa) * 32) + lane) * 4);
#pragma unroll
            for (int n = 0; n < 8; ++n) {
                uint2 Bf = *(const uint2*)(Bb + (((pb * 16 + cg * 8 + n) * 32) + lane) * 2);
#pragma unroll
                for (int m = 0; m < 4; ++m) mma16816(acc[m][n], Af[m], Bf);
            }
        }
        __syncthreads();   // all warps done reading this B buffer

        if (ch + 2 < NCH) {
            const char* src = (const char*)g_Bp + (size_t)(ch + 2) * CHB;
            const uint32_t dst = sBaddr + (ch & 1) * CHB;
            for (int k = tid; k < 3072; k += 256) cp16(dst + k * 16, src + k * 16);
            cp_commit();
        }

        // epilogue: score = -2*dot + ||e||^2, streaming argmin (codes ascending)
        const int cb = ch * 128 + cg * 64 + 2 * (lane & 3);
#pragma unroll
        for (int n = 0; n < 8; ++n) {
            const int c0 = cb + n * 8;
            const float ea = sE2[c0], eb = sE2[c0 + 1];
#pragma unroll
            for (int m = 0; m < 4; ++m) {
                const int ha = 2 * m, hb = 2 * m + 1;
                float s0 = fmaf(-2.f, acc[m][n][0], ea);
                float s1 = fmaf(-2.f, acc[m][n][1], eb);
                float s2 = fmaf(-2.f, acc[m][n][2], ea);
                float s3 = fmaf(-2.f, acc[m][n][3], eb);
                if (s0 < best[ha]) { best[ha] = s0; bidx[ha] = c0; }
                if (s1 < best[ha]) { best[ha] = s1; bidx[ha] = c0 + 1; }
                if (s2 < best[hb]) { best[hb] = s2; bidx[hb] = c0; }
                if (s3 < best[hb]) { best[hb] = s3; bidx[hb] = c0 + 1; }
            }
        }
    }

    // quad reduce (lanes 4q..4q+3 share rows), idx tie-break = smaller
#pragma unroll
    for (int h = 0; h < 8; ++h) {
#pragma unroll
        for (int off = 1; off < 4; off <<= 1) {
            float os = __shfl_xor_sync(0xffffffffu, best[h], off);
            int   oi = __shfl_xor_sync(0xffffffffu, bidx[h], off);
            if (os < best[h] || (os == best[h] && oi < bidx[h])) { best[h] = os; bidx[h] = oi; }
        }
    }
    if ((lane & 3) == 0) {
        const int q = lane >> 2;
#pragma unroll
        for (int h = 0; h < 8; ++h) {
            const int row = rg * 64 + (h >> 1) * 16 + q + (h & 1) * 8;
            sRF[row * 2 + cg] = best[h];
            sRI[row * 2 + cg] = bidx[h];
        }
    }
    __syncthreads();
    // merge the two code-groups per row, write results
    {
        const float b0 = sRF[tid * 2], b1 = sRF[tid * 2 + 1];
        const int i0 = sRI[tid * 2], i1 = sRI[tid * 2 + 1];
        const int fin = (b1 < b0 || (b1 == b0 && i1 < i0)) ? i1 : i0;
        const int grow = blockIdx.x * ROWS_CTA + tid;
        g_idx[grow] = fin;
        out_idxf[grow] = (float)fin;
        atomicAdd(&g_counts[fin], 1);
    }
}

// ---------------- gather + straight-through + commitment loss ----------------
__global__ void gather_kernel(const float* __restrict__ x,
                              const float* __restrict__ embed,
                              float* __restrict__ out_q) {
    __shared__ float warpsum[8];
    const int gid = blockIdx.x * blockDim.x + threadIdx.x;
    const int lin = gid * 4;
    const int t_i = lin & (TT - 1);
    const int d_i = (lin >> 11) & (DIM - 1);
    const int b_i = lin >> 17;

    float4 xv = *(const float4*)(x + lin);
    const int rowbase = (b_i << 11) + t_i;
    int4 id = *(const int4*)(g_idx + rowbase);

    float q0 = embed[id.x * DIM + d_i];
    float q1 = embed[id.y * DIM + d_i];
    float q2 = embed[id.z * DIM + d_i];
    float q3 = embed[id.w * DIM + d_i];

    float d0 = q0 - xv.x, d1 = q1 - xv.y, d2 = q2 - xv.z, d3 = q3 - xv.w;
    float4 ov = make_float4(xv.x + d0, xv.y + d1, xv.z + d2, xv.w + d3);
    *(float4*)(out_q + lin) = ov;

    float s = d0 * d0 + d1 * d1 + d2 * d2 + d3 * d3;
#pragma unroll
    for (int o = 16; o; o >>= 1) s += __shfl_down_sync(0xffffffffu, s, o);
    const int lane = threadIdx.x & 31, w = threadIdx.x >> 5;
    if (lane == 0) warpsum[w] = s;
    __syncthreads();
    if (w == 0) {
        float v = lane < 8 ? warpsum[lane] : 0.f;
#pragma unroll
        for (int o = 4; o; o >>= 1) v += __shfl_down_sync(0xffffffffu, v, o);
        if (lane == 0) atomicAdd(&g_sumsq, v);
    }
}

// ---------------- finalize ----------------
__global__ void finalize_kernel(float* __restrict__ out) {
    __shared__ float s1[32], s2[32];
    const int tid = threadIdx.x;
    float p = (float)g_counts[tid] * (1.0f / (float)NROWS);
    out[AVG_OFF + tid] = p;
    float t1 = p * logf(p + 1e-10f);
    float t2 = p * logf(p * (float)NUM_E + 1e-10f);
#pragma unroll
    for (int o = 16; o; o >>= 1) {
        t1 += __shfl_down_sync(0xffffffffu, t1, o);
        t2 += __shfl_down_sync(0xffffffffu, t2, o);
    }
    const int lane = tid & 31, w = tid >> 5;
    if (lane == 0) { s1[w] = t1; s2[w] = t2; }
    __syncthreads();
    if (w == 0) {
        float a = s1[lane], b = s2[lane];
#pragma unroll
        for (int o = 16; o; o >>= 1) {
            a += __shfl_down_sync(0xffffffffu, a, o);
            b += __shfl_down_sync(0xffffffffu, b, o);
        }
        if (lane == 0) {
            out[PERP_OFF]   = expf(-a);
            out[USAGE_OFF]  = b;
            out[COMMIT_OFF] = 0.25f * g_sumsq / (float)NELEM;
        }
    }
}

extern "C" void kernel_launch(void* const* d_in, const int* in_sizes, int n_in,
                              void* d_out, int out_size) {
    const float* x     = (const float*)d_in[0];
    const float* embed = (const float*)d_in[1];
    float* out = (float*)d_out;

    cudaFuncSetAttribute(vq_mma_kernel, cudaFuncAttributeMaxDynamicSharedMemorySize, SMEM_DYN);

    prep_kernel<<<1, 1024>>>(embed);
    vq_mma_kernel<<<NROWS / ROWS_CTA, 256, SMEM_DYN>>>(x, out + IDX_OFF);
    gather_kernel<<<NELEM / (256 * 4), 256>>>(x, embed, out);
    finalize_kernel<<<1, 1024>>>(out);
}

// round 4
// speedup vs baseline: 2.1564x; 1.6775x over previous
#include <cuda_runtime.h>
#include <cuda_fp16.h>
#include <cstdint>
#include <math.h>

// ---------------- problem constants ----------------
#define NUM_E 1024
#define DIM   64
#define TT    2048
#define BB    32
#define NROWS (BB * TT)          // 65536
#define NELEM (BB * DIM * TT)    // 4194304

// output layout (flattened tuple, fp32)
#define COMMIT_OFF 4194304
#define PERP_OFF   4194305
#define AVG_OFF    4194306
#define IDX_OFF    4195330
#define USAGE_OFF  4260866

// ---------------- tiling ----------------
#define ROWS_CTA 128                 // rows per CTA (8 m-tiles)
#define NCH      8                   // code chunks of 128
#define CHB      32768               // packed B chunk: 8 pkt * 16 nt * 32 * 8B

// smem offsets
#define SA_OFF   0                   // A frags: 8 mt * 8 pkt * 32 * 16B = 32KB
#define SB_OFF   32768               // B frags: 2 * 32KB
#define SE2_OFF  98304               // 4KB
#define SRF_OFF  102400              // 128*4 floats = 2KB
#define SRI_OFF  104448              // 128*4 ints   = 2KB
#define SMEM_DYN 106496

#define INV2048 4.8828125e-4f

// ---------------- device scratch ----------------
__device__ __align__(16) unsigned char g_Bp[NCH * CHB];  // packed B frags
__device__ float g_e2[NUM_E];
__device__ int   g_idx[NROWS];
__device__ int   g_counts[NUM_E];
__device__ float g_sumsq;

// ---------------- helpers ----------------
__device__ __forceinline__ uint32_t smem_u32(const void* p) {
    uint32_t a;
    asm("{ .reg .u64 t; cvta.to.shared.u64 t, %1; cvt.u32.u64 %0, t; }" : "=r"(a) : "l"(p));
    return a;
}
__device__ __forceinline__ void cp16(uint32_t saddr, const void* g) {
    asm volatile("cp.async.cg.shared.global [%0], [%1], 16;" :: "r"(saddr), "l"(g));
}
__device__ __forceinline__ void cp_commit() {
    asm volatile("cp.async.commit_group;" ::: "memory");
}
__device__ __forceinline__ void mma16816(float* d, const uint4 a, const uint2 b) {
    asm volatile(
        "mma.sync.aligned.m16n8k16.row.col.f32.f16.f16.f32 "
        "{%0,%1,%2,%3}, {%4,%5,%6,%7}, {%8,%9}, {%0,%1,%2,%3};"
        : "+f"(d[0]), "+f"(d[1]), "+f"(d[2]), "+f"(d[3])
        : "r"(a.x), "r"(a.y), "r"(a.z), "r"(a.w), "r"(b.x), "r"(b.y));
}
// scaled 2-split: v = h0 + h1/2048 with error ~2^-33
__device__ __forceinline__ void split2(float v, uint32_t& u0, uint32_t& u1) {
    __half h0 = __float2half_rn(v);
    float f0 = __half2float(h0);
    __half h1 = __float2half_rn((v - f0) * 2048.0f);
    u0 = (uint32_t)__half_as_ushort(h0);
    u1 = (uint32_t)__half_as_ushort(h1);
}

// ---------------- prep: pack codebook into B-fragment layout + norms ----------------
// 8 blocks x 128 threads, one code per thread
__global__ void prep_kernel(const float* __restrict__ embed) {
    const int c = blockIdx.x * 128 + threadIdx.x;
    const float* e = embed + (size_t)c * DIM;
    uint32_t h0[32], h1[32];
    float s = 0.f;
#pragma unroll 8
    for (int j = 0; j < 32; ++j) {
        float2 v = *(const float2*)(e + 2 * j);
        s += v.x * v.x + v.y * v.y;
        uint32_t a0, a1, b0, b1;
        split2(v.x, a0, a1);
        split2(v.y, b0, b1);
        h0[j] = a0 | (b0 << 16);
        h1[j] = a1 | (b1 << 16);
    }
    g_e2[c] = s;
    g_counts[c] = 0;
    if (c == 0) g_sumsq = 0.f;

    const int chunk = c >> 7, n_in = c & 127, nt = n_in >> 3, lq = n_in & 7;
    uint32_t* dstb = (uint32_t*)(g_Bp + (size_t)chunk * CHB);
#pragma unroll
    for (int pkt = 0; pkt < 8; ++pkt) {
        const uint32_t* hp = (pkt < 4) ? h0 : h1;
        const int kb = (pkt & 3) * 8;
#pragma unroll
        for (int cc = 0; cc < 4; ++cc) {
            uint32_t* d = dstb + (((pkt * 16 + nt) * 32) + 4 * lq + cc) * 2;
            d[0] = hp[kb + cc];       // k = 2cc, 2cc+1
            d[1] = hp[kb + 4 + cc];   // k = 2cc+8, 2cc+9
        }
    }
}

// ---------------- main: HMMA distance GEMM + fused argmin ----------------
// 512 threads = 16 warps = 4 row-groups x 4 code-groups; 128 rows/CTA
__global__ void __launch_bounds__(512, 1)
vq_mma_kernel(const float* __restrict__ x, float* __restrict__ out_idxf) {
    extern __shared__ char sm[];
    uint32_t* sA  = (uint32_t*)(sm + SA_OFF);
    float*    sE2 = (float*)(sm + SE2_OFF);
    float*    sRF = (float*)(sm + SRF_OFF);
    int*      sRI = (int*)(sm + SRI_OFF);
    const uint32_t sBaddr = smem_u32(sm + SB_OFF);

    const int tid = threadIdx.x, lane = tid & 31, w = tid >> 5;
    const int rg = w & 3, cg = w >> 2;   // 4 row-groups x 4 code-groups

    // prefetch B chunks 0,1
    {
        const char* src0 = (const char*)g_Bp;
        for (int k = tid; k < CHB / 16; k += 512) cp16(sBaddr + k * 16, src0 + k * 16);
        cp_commit();
        const char* src1 = (const char*)g_Bp + CHB;
        for (int k = tid; k < CHB / 16; k += 512) cp16(sBaddr + CHB + k * 16, src1 + k * 16);
        cp_commit();
    }

    // build A fragments: thread = (row, quarter); quarter q covers dims 16q..16q+15
    {
        const int r = tid >> 2, q = tid & 3;
        const int grow = blockIdx.x * ROWS_CTA + r;
        const float* xp = x + (size_t)(grow >> 11) * (DIM * TT) + (grow & (TT - 1));
        uint32_t h0[8], h1[8];
#pragma unroll
        for (int j = 0; j < 8; ++j) {
            float va = xp[(size_t)(16 * q + 2 * j) * TT];
            float vb = xp[(size_t)(16 * q + 2 * j + 1) * TT];
            uint32_t a0, a1, b0, b1;
            split2(va, a0, a1);
            split2(vb, b0, b1);
            h0[j] = a0 | (b0 << 16);
            h1[j] = a1 | (b1 << 16);
        }
        const int mt = r >> 4, rr = r & 15;
        const int wsel = (rr < 8) ? 0 : 1;   // a0/a2 vs a1/a3 rows
#pragma unroll
        for (int sp = 0; sp < 2; ++sp) {
            const int pkt = sp * 4 + q;
            const uint32_t* hp = sp ? h1 : h0;
#pragma unroll
            for (int c = 0; c < 4; ++c) {
                uint32_t* dst = sA + (((mt * 8 + pkt) * 32) + 4 * (rr & 7) + c) * 4 + wsel;
                dst[0] = hp[c];       // a0 / a1
                dst[2] = hp[4 + c];   // a2 / a3
            }
        }
        for (int i = tid; i < NUM_E; i += 512) sE2[i] = g_e2[i];
    }
    __syncthreads();

    // logical k-tiles: x0e0 (acc0), x0e1 (acc1), x1e0 (acc1)
    const int PA_[12]  = {0,1,2,3, 0,1,2,3, 4,5,6,7};
    const int PB_[12]  = {0,1,2,3, 4,5,6,7, 0,1,2,3};
    const int ACC_[12] = {0,0,0,0, 1,1,1,1, 1,1,1,1};

    float best[4];
    int   bidx[4];
#pragma unroll
    for (int h = 0; h < 4; ++h) { best[h] = 3.4e38f; bidx[h] = 0; }

    for (int ch = 0; ch < NCH; ++ch) {
        if (ch < NCH - 1) asm volatile("cp.async.wait_group 1;" ::: "memory");
        else              asm volatile("cp.async.wait_group 0;" ::: "memory");
        __syncthreads();
        const uint32_t* Bb = (const uint32_t*)(sm + SB_OFF + (ch & 1) * CHB);

        float acc[2][2][4][4];   // [set][m][n][j]
#pragma unroll
        for (int s = 0; s < 2; ++s)
#pragma unroll
            for (int m = 0; m < 2; ++m)
#pragma unroll
                for (int n = 0; n < 4; ++n)
#pragma unroll
                    for (int j = 0; j < 4; ++j) acc[s][m][n][j] = 0.f;

#pragma unroll
        for (int lkt = 0; lkt < 12; ++lkt) {
            const int pa = PA_[lkt], pb = PB_[lkt], as = ACC_[lkt];
            uint4 Af[2];
#pragma unroll
            for (int m = 0; m < 2; ++m)
                Af[m] = *(const uint4*)(sA + ((((rg * 2 + m) * 8 + pa) * 32) + lane) * 4);
#pragma unroll
            for (int n = 0; n < 4; ++n) {
                uint2 Bf = *(const uint2*)(Bb + (((pb * 16 + cg * 4 + n) * 32) + lane) * 2);
#pragma unroll
                for (int m = 0; m < 2; ++m) mma16816(acc[as][m][n], Af[m], Bf);
            }
        }
        __syncthreads();   // all warps done reading this B buffer

        if (ch + 2 < NCH) {
            const char* src = (const char*)g_Bp + (size_t)(ch + 2) * CHB;
            const uint32_t dst = sBaddr + (ch & 1) * CHB;
            for (int k = tid; k < CHB / 16; k += 512) cp16(dst + k * 16, src + k * 16);
            cp_commit();
        }

        // epilogue: dot = acc0 + acc1/2048; score = -2*dot + ||e||^2
        const int cb = ch * 128 + cg * 32 + 2 * (lane & 3);
#pragma unroll
        for (int n = 0; n < 4; ++n) {
            const int c0 = cb + n * 8;
            const float ea = sE2[c0], eb = sE2[c0 + 1];
#pragma unroll
            for (int m = 0; m < 2; ++m) {
                const int ha = 2 * m, hb = 2 * m + 1;
                float d0 = fmaf(acc[1][m][n][0], INV2048, acc[0][m][n][0]);
                float d1 = fmaf(acc[1][m][n][1], INV2048, acc[0][m][n][1]);
                float d2 = fmaf(acc[1][m][n][2], INV2048, acc[0][m][n][2]);
                float d3 = fmaf(acc[1][m][n][3], INV2048, acc[0][m][n][3]);
                float s0 = fmaf(-2.f, d0, ea);
                float s1 = fmaf(-2.f, d1, eb);
                float s2 = fmaf(-2.f, d2, ea);
                float s3 = fmaf(-2.f, d3, eb);
                if (s0 < best[ha]) { best[ha] = s0; bidx[ha] = c0; }
                if (s1 < best[ha]) { best[ha] = s1; bidx[ha] = c0 + 1; }
                if (s2 < best[hb]) { best[hb] = s2; bidx[hb] = c0; }
                if (s3 < best[hb]) { best[hb] = s3; bidx[hb] = c0 + 1; }
            }
        }
    }

    // quad reduce (lanes 4q..4q+3 share rows), idx tie-break = smaller
#pragma unroll
    for (int h = 0; h < 4; ++h) {
#pragma unroll
        for (int off = 1; off < 4; off <<= 1) {
            float os = __shfl_xor_sync(0xffffffffu, best[h], off);
            int   oi = __shfl_xor_sync(0xffffffffu, bidx[h], off);
            if (os < best[h] || (os == best[h] && oi < bidx[h])) { best[h] = os; bidx[h] = oi; }
        }
    }
    if ((lane & 3) == 0) {
        const int q = lane >> 2;
#pragma unroll
        for (int h = 0; h < 4; ++h) {
            const int m = h >> 1, hb = h & 1;
            const int row = rg * 32 + m * 16 + hb * 8 + q;
            sRF[row * 4 + cg] = best[h];
            sRI[row * 4 + cg] = bidx[h];
        }
    }
    __syncthreads();
    // merge the four code-groups per row, write results
    if (tid < ROWS_CTA) {
        float bv = sRF[tid * 4];
        int   bi = sRI[tid * 4];
#pragma unroll
        for (int g = 1; g < 4; ++g) {
            float v = sRF[tid * 4 + g];
            int   i = sRI[tid * 4 + g];
            if (v < bv || (v == bv && i < bi)) { bv = v; bi = i; }
        }
        const int grow = blockIdx.x * ROWS_CTA + tid;
        g_idx[grow] = bi;
        out_idxf[grow] = (float)bi;
        atomicAdd(&g_counts[bi], 1);
    }
}

// ---------------- gather + straight-through + commitment loss ----------------
__global__ void gather_kernel(const float* __restrict__ x,
                              const float* __restrict__ embed,
                              float* __restrict__ out_q) {
    __shared__ float warpsum[8];
    const int gid = blockIdx.x * blockDim.x + threadIdx.x;
    const int lin = gid * 4;
    const int t_i = lin & (TT - 1);
    const int d_i = (lin >> 11) & (DIM - 1);
    const int b_i = lin >> 17;

    float4 xv = *(const float4*)(x + lin);
    const int rowbase = (b_i << 11) + t_i;
    int4 id = *(const int4*)(g_idx + rowbase);

    float q0 = embed[id.x * DIM + d_i];
    float q1 = embed[id.y * DIM + d_i];
    float q2 = embed[id.z * DIM + d_i];
    float q3 = embed[id.w * DIM + d_i];

    float d0 = q0 - xv.x, d1 = q1 - xv.y, d2 = q2 - xv.z, d3 = q3 - xv.w;
    float4 ov = make_float4(xv.x + d0, xv.y + d1, xv.z + d2, xv.w + d3);
    *(float4*)(out_q + lin) = ov;

    float s = d0 * d0 + d1 * d1 + d2 * d2 + d3 * d3;
#pragma unroll
    for (int o = 16; o; o >>= 1) s += __shfl_down_sync(0xffffffffu, s, o);
    const int lane = threadIdx.x & 31, w = threadIdx.x >> 5;
    if (lane == 0) warpsum[w] = s;
    __syncthreads();
    if (w == 0) {
        float v = lane < 8 ? warpsum[lane] : 0.f;
#pragma unroll
        for (int o = 4; o; o >>= 1) v += __shfl_down_sync(0xffffffffu, v, o);
        if (lane == 0) atomicAdd(&g_sumsq, v);
    }
}

// ---------------- finalize ----------------
__global__ void finalize_kernel(float* __restrict__ out) {
    __shared__ float s1[32], s2[32];
    const int tid = threadIdx.x;
    float p = (float)g_counts[tid] * (1.0f / (float)NROWS);
    out[AVG_OFF + tid] = p;
    float t1 = p * logf(p + 1e-10f);
    float t2 = p * logf(p * (float)NUM_E + 1e-10f);
#pragma unroll
    for (int o = 16; o; o >>= 1) {
        t1 += __shfl_down_sync(0xffffffffu, t1, o);
        t2 += __shfl_down_sync(0xffffffffu, t2, o);
    }
    const int lane = tid & 31, w = tid >> 5;
    if (lane == 0) { s1[w] = t1; s2[w] = t2; }
    __syncthreads();
    if (w == 0) {
        float a = s1[lane], b = s2[lane];
#pragma unroll
        for (int o = 16; o; o >>= 1) {
            a += __shfl_down_sync(0xffffffffu, a, o);
            b += __shfl_down_sync(0xffffffffu, b, o);
        }
        if (lane == 0) {
            out[PERP_OFF]   = expf(-a);
            out[USAGE_OFF]  = b;
            out[COMMIT_OFF] = 0.25f * g_sumsq / (float)NELEM;
        }
    }
}

extern "C" void kernel_launch(void* const* d_in, const int* in_sizes, int n_in,
                              void* d_out, int out_size) {
    const float* x     = (const float*)d_in[0];
    const float* embed = (const float*)d_in[1];
    float* out = (float*)d_out;

    cudaFuncSetAttribute(vq_mma_kernel, cudaFuncAttributeMaxDynamicSharedMemorySize, SMEM_DYN);

    prep_kernel<<<8, 128>>>(embed);
    vq_mma_kernel<<<NROWS / ROWS_CTA, 512, SMEM_DYN>>>(x, out + IDX_OFF);
    gather_kernel<<<NELEM / (256 * 4), 256>>>(x, embed, out);
    finalize_kernel<<<1, 1024>>>(out);
}